// round 15
// baseline (speedup 1.0000x reference)
#include <cuda_runtime.h>
#include <cuda_bf16.h>

#define TT 150
#define VV 2048
#define CC 16
#define LL 64
#define EE 32768
#define NV 16384
#define L3 192
#define ZST 144
#define NST 80

typedef unsigned long long u64;
typedef unsigned int u32;

__device__ float g_xe[(size_t)TT * NV * LL];
__device__ float g_agg[(size_t)TT * NV * LL];
__device__ float g_hd[NV * LL];
__device__ float g_pre[NV * LL];
__device__ float g_Wgdi[LL * L3];
__device__ float g_Wgci[LL * L3];
__device__ int   g_off[VV + 1];
__device__ int   g_eid[EE];
__device__ u64   g_epk[EE];

__device__ __forceinline__ u64 pk2(float x, float y) {
    u64 r; asm("mov.b64 %0, {%1, %2};" : "=l"(r) : "f"(x), "f"(y)); return r;
}
__device__ __forceinline__ void upk2(u64 v, float& x, float& y) {
    asm("mov.b64 {%0, %1}, %2;" : "=f"(x), "=f"(y) : "l"(v));
}
__device__ __forceinline__ void fma2(u64& d, u64 a, u64 b) {
    asm("fma.rn.f32x2 %0, %1, %2, %0;" : "+l"(d) : "l"(a), "l"(b));
}
__device__ __forceinline__ float sigf(float x) {
    x = fminf(fmaxf(x, -20.f), 20.f);
    return __fdividef(1.f, 1.f + __expf(-x));
}
__device__ __forceinline__ float tanh_f(float x) {
    x = fminf(fmaxf(x, -10.f), 10.f);
    float e = __expf(-2.f * x);
    return __fdividef(1.f - e, 1.f + e);
}
__device__ __forceinline__ void pksplit(float x0, float x1, u32& ph, u32& pl) {
    u32 hp; asm("cvt.rn.bf16x2.f32 %0, %1, %2;" : "=r"(hp) : "f"(x1), "f"(x0));
    float h0 = __uint_as_float(hp << 16);
    float h1 = __uint_as_float(hp & 0xffff0000u);
    u32 lp; asm("cvt.rn.bf16x2.f32 %0, %1, %2;" : "=r"(lp) : "f"(x1 - h1), "f"(x0 - h0));
    ph = hp; pl = lp;
}
__device__ __forceinline__ void mma16816(float* c, const u32* a, const u32* b) {
    asm volatile("mma.sync.aligned.m16n8k16.row.col.f32.bf16.bf16.f32 "
        "{%0,%1,%2,%3}, {%4,%5,%6,%7}, {%8,%9}, {%0,%1,%2,%3};"
        : "+f"(c[0]), "+f"(c[1]), "+f"(c[2]), "+f"(c[3])
        : "r"(a[0]), "r"(a[1]), "r"(a[2]), "r"(a[3]), "r"(b[0]), "r"(b[1]));
}
// 3-term split MMA from interleaved B frag (one LDS.128)
__device__ __forceinline__ void mma3(float* c, const u32* ah, const u32* al, const u32* p) {
    uint4 q = *(const uint4*)p;
    u32 bh[2] = { q.x, q.z }, bl[2] = { q.y, q.w };
    mma16816(c, ah, bh);
    mma16816(c, ah, bl);
    mma16816(c, al, bh);
}
__device__ __forceinline__ void afrag(const float v[8][4], int kt, u32* ah, u32* al) {
    #pragma unroll
    for (int i = 0; i < 4; i++) {
        int j = 2 * kt + (i >> 1);
        int q0 = (i & 1) * 2;
        pksplit(v[j][q0], v[j][q0 + 1], ah[i], al[i]);
    }
}

// ---------------- encoder ----------------
__global__ void __launch_bounds__(256) k_enc(const float* __restrict__ x,
                                             const float* __restrict__ Wenc,
                                             const float* __restrict__ benc) {
    __shared__ float sx[CC * TT];
    __shared__ float2 sW[CC * 32];
    __shared__ float2 sb[32];
    int tid = threadIdx.x, r = blockIdx.x;
    for (int i = tid; i < CC * TT; i += 256) sx[i] = x[(size_t)r * CC * TT + i];
    for (int i = tid; i < CC * 32; i += 256) {
        int c = i >> 5, l = i & 31;
        sW[i] = make_float2(Wenc[c * LL + l], Wenc[c * LL + l + 32]);
    }
    if (tid < 32) sb[tid] = make_float2(benc[tid], benc[tid + 32]);
    __syncthreads();
    int wid = tid >> 5, lane = tid & 31;
    for (int t = wid; t < TT; t += 8) {
        u64 acc = pk2(sb[lane].x, sb[lane].y);
        #pragma unroll
        for (int c = 0; c < CC; c++) {
            float xs = sx[c * TT + t];
            fma2(acc, pk2(xs, xs), pk2(sW[c * 32 + lane].x, sW[c * 32 + lane].y));
        }
        float ax, ay; upk2(acc, ax, ay);
        size_t o = ((size_t)t * NV + r) * LL;
        g_xe[o + lane] = ax;
        g_xe[o + lane + 32] = ay;
    }
}

// ---------------- fused CSR build + weight combines + edge packing ----------------
__global__ void __launch_bounds__(1024) k_csr(const int* __restrict__ ei,
        const float* __restrict__ attr,
        const float* __restrict__ Wgd, const float* __restrict__ gdWi,
        const float* __restrict__ Wgc, const float* __restrict__ gcWi) {
    __shared__ int scnt[VV];
    __shared__ int sfil[VV];
    int tid = threadIdx.x;
    for (int i = tid; i < VV; i += 1024) { scnt[i] = 0; sfil[i] = 0; }
    __syncthreads();
    for (int e = tid; e < EE; e += 1024) atomicAdd(&scnt[ei[EE + e]], 1);
    __syncthreads();
    if (tid == 0) {
        int acc = 0;
        for (int v = 0; v < VV; v++) { g_off[v] = acc; acc += scnt[v]; }
        g_off[VV] = acc;
    }
    __syncthreads();
    for (int e = tid; e < EE; e += 1024) {
        int d = ei[EE + e];
        int p = g_off[d] + atomicAdd(&sfil[d], 1);
        g_eid[p] = e;
    }
    __syncthreads();
    for (int v = tid; v < VV; v += 1024) {
        int s = g_off[v], en = g_off[v + 1];
        for (int i = s + 1; i < en; i++) {
            int key = g_eid[i];
            int j = i - 1;
            while (j >= s && g_eid[j] > key) { g_eid[j + 1] = g_eid[j]; j--; }
            g_eid[j + 1] = key;
        }
    }
    __syncthreads();
    for (int p = tid; p < EE; p += 1024) {
        int e = g_eid[p];
        g_epk[p] = (u64)(u32)ei[e] | ((u64)__float_as_uint(attr[e]) << 32);
    }
    for (int idx = tid; idx < 2 * LL * L3; idx += 1024) {
        int which = idx >= LL * L3;
        int rem = which ? idx - LL * L3 : idx;
        int k = rem / L3, j = rem - k * L3;
        const float* A = which ? Wgc : Wgd;
        const float* B = which ? gcWi : gdWi;
        float acc = 0.f;
        #pragma unroll 8
        for (int m = 0; m < LL; m++) acc = fmaf(A[k * LL + m], B[m * L3 + j], acc);
        (which ? g_Wgci : g_Wgdi)[rem] = acc;
    }
}

// ---------------- aggregation (packed edges, 2x unroll) ----------------
__global__ void __launch_bounds__(256) k_agg() {
    int tid = threadIdx.x, wid = tid >> 5, lane = tid & 31;
    int gw = blockIdx.x * 8 + wid, nw = gridDim.x * 8;
    for (int task = gw; task < TT * NV; task += nw) {
        int t = task >> 14;
        int r = task & (NV - 1);
        int v = r & (VV - 1);
        const float* xb = g_xe + ((size_t)t * NV + (r & ~(VV - 1))) * LL;
        int s0 = g_off[v], s1 = g_off[v + 1];
        u64 acc = 0ULL, acc2 = 0ULL;
        int e = s0;
        for (; e + 1 < s1; e += 2) {
            u64 p0 = g_epk[e], p1 = g_epk[e + 1];
            int sA = (int)(u32)(p0 & 0xffffffffu);
            int sB = (int)(u32)(p1 & 0xffffffffu);
            float wA = __uint_as_float((u32)(p0 >> 32));
            float wB = __uint_as_float((u32)(p1 >> 32));
            float2 vA = ((const float2*)(xb + (size_t)sA * LL))[lane];
            float2 vB = ((const float2*)(xb + (size_t)sB * LL))[lane];
            fma2(acc, pk2(wA, wA), pk2(vA.x, vA.y));
            fma2(acc2, pk2(wB, wB), pk2(vB.x, vB.y));
        }
        if (e < s1) {
            u64 p0 = g_epk[e];
            int sA = (int)(u32)(p0 & 0xffffffffu);
            float wA = __uint_as_float((u32)(p0 >> 32));
            float2 vA = ((const float2*)(xb + (size_t)sA * LL))[lane];
            fma2(acc, pk2(wA, wA), pk2(vA.x, vA.y));
        }
        float a0, a1, b0, b1; upk2(acc, a0, a1); upk2(acc2, b0, b1);
        ((float2*)(g_agg + (size_t)task * LL))[lane] = make_float2(a0 + b0, a1 + b1);
    }
}

// ---------------- scan1: HMMA register-chained domain GRU (interleaved B) ----------------
__global__ void __launch_bounds__(256, 1) k_scan1(const float* __restrict__ Wh,
                                                  const float* __restrict__ bg) {
    extern __shared__ u32 s1m[];
    u32* Bzr = s1m;                    // 128 cols * ZST
    u32* Bni = Bzr + 128 * ZST;        // 64 cols * NST
    u32* Bnh = Bni + 64 * NST;
    float* sbg = (float*)(Bnh + 64 * NST);
    int tid = threadIdx.x;
    for (int i = tid; i < 128 * 64; i += 256) {
        int c = i >> 6, w = i & 63;
        int k0 = 16 * (w >> 3) + ((w & 7) & ~1) + 8 * (w & 1);
        float v0 = (k0 < 64) ? g_Wgdi[k0 * L3 + c] : Wh[(k0 - 64) * L3 + c];
        float v1 = (k0 + 1 < 64) ? g_Wgdi[(k0 + 1) * L3 + c] : Wh[(k0 + 1 - 64) * L3 + c];
        pksplit(v0, v1, Bzr[c * ZST + 2 * w], Bzr[c * ZST + 2 * w + 1]);
    }
    for (int i = tid; i < 64 * 32; i += 256) {
        int c = i >> 5, w = i & 31;
        int k0 = 16 * (w >> 3) + ((w & 7) & ~1) + 8 * (w & 1);
        pksplit(g_Wgdi[k0 * L3 + 128 + c], g_Wgdi[(k0 + 1) * L3 + 128 + c],
                Bni[c * NST + 2 * w], Bni[c * NST + 2 * w + 1]);
        pksplit(Wh[k0 * L3 + 128 + c], Wh[(k0 + 1) * L3 + 128 + c],
                Bnh[c * NST + 2 * w], Bnh[c * NST + 2 * w + 1]);
    }
    if (tid < 192) sbg[tid] = bg[tid];
    __syncthreads();
    int lane = tid & 31, wid = tid >> 5;
    int g = lane >> 2, tig = lane & 3;
    int grl = blockIdx.x * 128 + wid * 16 + g, grh = grl + 8;
    float h[8][4];
    #pragma unroll
    for (int j = 0; j < 8; j++)
        #pragma unroll
        for (int q = 0; q < 4; q++) h[j][q] = 0.f;
    for (int t = 0; t < TT; t++) {
        float cz[8][4] = {}, crr[8][4] = {}, cni[8][4] = {}, cnh[8][4] = {};
        const float* aggt = g_agg + (size_t)t * NV * 64;
        #pragma unroll
        for (int kt = 0; kt < 4; kt++) {
            float2 a0 = *(const float2*)(aggt + (size_t)grl * 64 + 16 * kt + 2 * tig);
            float2 a1 = *(const float2*)(aggt + (size_t)grh * 64 + 16 * kt + 2 * tig);
            float2 a2 = *(const float2*)(aggt + (size_t)grl * 64 + 16 * kt + 8 + 2 * tig);
            float2 a3 = *(const float2*)(aggt + (size_t)grh * 64 + 16 * kt + 8 + 2 * tig);
            u32 ah[4], al[4];
            pksplit(a0.x, a0.y, ah[0], al[0]);
            pksplit(a1.x, a1.y, ah[1], al[1]);
            pksplit(a2.x, a2.y, ah[2], al[2]);
            pksplit(a3.x, a3.y, ah[3], al[3]);
            int wo = 16 * kt + 4 * tig;
            #pragma unroll
            for (int j = 0; j < 8; j++) {
                mma3(cz[j], ah, al, &Bzr[(8 * j + g) * ZST + wo]);
                mma3(crr[j], ah, al, &Bzr[(64 + 8 * j + g) * ZST + wo]);
                mma3(cni[j], ah, al, &Bni[(8 * j + g) * NST + wo]);
            }
        }
        #pragma unroll
        for (int kt = 0; kt < 4; kt++) {
            u32 ah[4], al[4]; afrag(h, kt, ah, al);
            int wo = 16 * (kt + 4) + 4 * tig;
            int wn = 16 * kt + 4 * tig;
            #pragma unroll
            for (int j = 0; j < 8; j++) {
                mma3(cz[j], ah, al, &Bzr[(8 * j + g) * ZST + wo]);
                mma3(crr[j], ah, al, &Bzr[(64 + 8 * j + g) * ZST + wo]);
                mma3(cnh[j], ah, al, &Bnh[(8 * j + g) * NST + wn]);
            }
        }
        #pragma unroll
        for (int j = 0; j < 8; j++)
            #pragma unroll
            for (int q = 0; q < 4; q++) {
                int col = 8 * j + 2 * tig + (q & 1);
                float z = sigf(cz[j][q] + sbg[col]);
                float r = sigf(crr[j][q] + sbg[64 + col]);
                float n = tanh_f(cni[j][q] + sbg[128 + col] + r * cnh[j][q]);
                h[j][q] = (1.f - z) * n + z * h[j][q];
            }
    }
    #pragma unroll
    for (int j = 0; j < 8; j++)
        #pragma unroll
        for (int q = 0; q < 4; q++) {
            int row = (q < 2) ? grl : grh;
            int col = 8 * j + 2 * tig + (q & 1);
            g_hd[(size_t)row * 64 + col] = h[j][q];
        }
}

// ---------------- z_D + pre_ode ----------------
__global__ void __launch_bounds__(256) k_zd(const float* __restrict__ Wd1, const float* __restrict__ bd1,
                                            const float* __restrict__ Wd2, const float* __restrict__ bd2,
                                            const float* __restrict__ oW1, const float* __restrict__ ob1) {
    extern __shared__ u64 smz[];
    u64* sA = smz;
    u64* sB = sA + 2048;
    u64* sC = sB + 2048;
    u64* b1 = sC + 2048;
    u64* b2 = b1 + 32;
    u64* b3 = b2 + 32;
    int tid = threadIdx.x;
    for (int i = tid; i < 2048; i += 256) {
        int k = i >> 5, l = i & 31;
        sA[i] = pk2(Wd1[k * 64 + l], Wd1[k * 64 + l + 32]);
        sB[i] = pk2(Wd2[k * 64 + l], Wd2[k * 64 + l + 32]);
        sC[i] = pk2(oW1[(64 + k) * 64 + l], oW1[(64 + k) * 64 + l + 32]);
    }
    if (tid < 32) {
        b1[tid] = pk2(bd1[tid], bd1[tid + 32]);
        b2[tid] = pk2(bd2[tid], bd2[tid + 32]);
        b3[tid] = pk2(ob1[tid], ob1[tid + 32]);
    }
    __syncthreads();
    int wid = tid >> 5, lane = tid & 31;
    for (int r = blockIdx.x * 8 + wid; r < NV; r += gridDim.x * 8) {
        size_t o = (size_t)r * LL + lane;
        float2 hd = make_float2(g_hd[o], g_hd[o + 32]);
        u64 u = b1[lane];
        #pragma unroll
        for (int half = 0; half < 2; half++)
            #pragma unroll 8
            for (int kk = 0; kk < 32; kk++) {
                float hv = __shfl_sync(0xffffffffu, half ? hd.y : hd.x, kk);
                fma2(u, pk2(hv, hv), sA[(half * 32 + kk) * 32 + lane]);
            }
        float ux, uy; upk2(u, ux, uy);
        float2 uf = make_float2(tanh_f(ux), tanh_f(uy));
        u64 v = b2[lane];
        #pragma unroll
        for (int half = 0; half < 2; half++)
            #pragma unroll 8
            for (int kk = 0; kk < 32; kk++) {
                float uv = __shfl_sync(0xffffffffu, half ? uf.y : uf.x, kk);
                fma2(v, pk2(uv, uv), sB[(half * 32 + kk) * 32 + lane]);
            }
        float vx, vy; upk2(v, vx, vy);
        float2 vf = make_float2(vx, vy);
        u64 p = b3[lane];
        #pragma unroll
        for (int half = 0; half < 2; half++)
            #pragma unroll 8
            for (int kk = 0; kk < 32; kk++) {
                float vv = __shfl_sync(0xffffffffu, half ? vf.y : vf.x, kk);
                fma2(p, pk2(vv, vv), sC[(half * 32 + kk) * 32 + lane]);
            }
        float px, py; upk2(p, px, py);
        g_pre[o] = px;
        g_pre[o + 32] = py;
    }
}

// ---------------- scan2: HMMA register-chained main scan (interleaved B, fused decode) ----------------
__global__ void __launch_bounds__(256, 1) k_scan2(
        const float* __restrict__ Wh, const float* __restrict__ bgc,
        const float* __restrict__ oW1, const float* __restrict__ oW2,
        const float* __restrict__ ob2,
        const float* __restrict__ Wdec, const float* __restrict__ bdec,
        float* __restrict__ out) {
    extern __shared__ u32 s2[];
    u32* Bzr = s2;                      // 128 * ZST
    u32* Bni = Bzr + 128 * ZST;         // 64 * NST
    u32* Bnh = Bni + 64 * NST;
    u32* B1  = Bnh + 64 * NST;
    u32* B2  = B1 + 64 * NST;
    u32* B4  = B2 + 64 * NST;           // 16 * NST
    float* spre = (float*)(B4 + 16 * NST);  // 128 * 72
    float* sbg  = spre + 128 * 72;
    float* sb2  = sbg + 192;
    float* sbd  = sb2 + 64;
    int tid = threadIdx.x;
    for (int i = tid; i < 128 * 64; i += 256) {
        int c = i >> 6, w = i & 63;
        int k0 = 16 * (w >> 3) + ((w & 7) & ~1) + 8 * (w & 1);
        float v0 = (k0 < 64) ? g_Wgci[k0 * L3 + c] : Wh[(k0 - 64) * L3 + c];
        float v1 = (k0 + 1 < 64) ? g_Wgci[(k0 + 1) * L3 + c] : Wh[(k0 + 1 - 64) * L3 + c];
        pksplit(v0, v1, Bzr[c * ZST + 2 * w], Bzr[c * ZST + 2 * w + 1]);
    }
    for (int i = tid; i < 64 * 32; i += 256) {
        int c = i >> 5, w = i & 31;
        int k0 = 16 * (w >> 3) + ((w & 7) & ~1) + 8 * (w & 1);
        pksplit(g_Wgci[k0 * L3 + 128 + c], g_Wgci[(k0 + 1) * L3 + 128 + c],
                Bni[c * NST + 2 * w], Bni[c * NST + 2 * w + 1]);
        pksplit(Wh[k0 * L3 + 128 + c], Wh[(k0 + 1) * L3 + 128 + c],
                Bnh[c * NST + 2 * w], Bnh[c * NST + 2 * w + 1]);
        pksplit(oW1[k0 * 64 + c], oW1[(k0 + 1) * 64 + c],
                B1[c * NST + 2 * w], B1[c * NST + 2 * w + 1]);
        pksplit(oW2[k0 * 64 + c], oW2[(k0 + 1) * 64 + c],
                B2[c * NST + 2 * w], B2[c * NST + 2 * w + 1]);
    }
    for (int i = tid; i < 16 * 32; i += 256) {
        int c = i >> 5, w = i & 31;
        int k0 = 16 * (w >> 3) + ((w & 7) & ~1) + 8 * (w & 1);
        pksplit(Wdec[k0 * CC + c], Wdec[(k0 + 1) * CC + c],
                B4[c * NST + 2 * w], B4[c * NST + 2 * w + 1]);
    }
    int R0b = blockIdx.x * 128;
    for (int i = tid; i < 128 * 32; i += 256) {
        int r = i >> 5, p = i & 31;
        ((float2*)spre)[r * 36 + p] = ((const float2*)(g_pre + (size_t)(R0b + r) * 64))[p];
    }
    if (tid < 192) sbg[tid] = bgc[tid];
    if (tid < 64) sb2[tid] = ob2[tid];
    if (tid < 16) sbd[tid] = bdec[tid];
    __syncthreads();

    int lane = tid & 31, wid = tid >> 5;
    int g = lane >> 2, tig = lane & 3;
    int rl = wid * 16 + g, rh = rl + 8;
    int grl = R0b + rl, grh = R0b + rh;
    float h[8][4];
    #pragma unroll
    for (int j = 0; j < 8; j++) {
        float2 a = *(const float2*)(g_xe + (size_t)grl * 64 + 8 * j + 2 * tig);
        float2 b = *(const float2*)(g_xe + (size_t)grh * 64 + 8 * j + 2 * tig);
        h[j][0] = a.x; h[j][1] = a.y; h[j][2] = b.x; h[j][3] = b.y;
    }
    for (int t = 1; t < TT; t++) {
        // fused: decode h_{t-1} + R1 (u = pre + h @ W1top), sharing h frags
        float cu[8][4] = {}, cd[2][4] = {};
        #pragma unroll
        for (int kt = 0; kt < 4; kt++) {
            u32 ah[4], al[4]; afrag(h, kt, ah, al);
            int wo = 16 * kt + 4 * tig;
            #pragma unroll
            for (int j = 0; j < 8; j++) mma3(cu[j], ah, al, &B1[(8 * j + g) * NST + wo]);
            #pragma unroll
            for (int j = 0; j < 2; j++) mma3(cd[j], ah, al, &B4[(8 * j + g) * NST + wo]);
        }
        #pragma unroll
        for (int j = 0; j < 2; j++)
            #pragma unroll
            for (int q = 0; q < 4; q++) {
                int row = (q < 2) ? grl : grh;
                int col = 8 * j + 2 * tig + (q & 1);
                out[((size_t)row * CC + col) * TT + (t - 1)] = cd[j][q] + sbd[col];
            }
        float uf[8][4];
        #pragma unroll
        for (int j = 0; j < 8; j++) {
            float2 p0 = ((const float2*)spre)[rl * 36 + 4 * j + tig];
            float2 p1 = ((const float2*)spre)[rh * 36 + 4 * j + tig];
            uf[j][0] = tanh_f(cu[j][0] + p0.x); uf[j][1] = tanh_f(cu[j][1] + p0.y);
            uf[j][2] = tanh_f(cu[j][2] + p1.x); uf[j][3] = tanh_f(cu[j][3] + p1.y);
        }
        // R2: ho = h + uf @ W2 + b2
        float ho[8][4];
        {
            float cd2[8][4] = {};
            #pragma unroll
            for (int kt = 0; kt < 4; kt++) {
                u32 ah[4], al[4]; afrag(uf, kt, ah, al);
                int wo = 16 * kt + 4 * tig;
                #pragma unroll
                for (int j = 0; j < 8; j++) mma3(cd2[j], ah, al, &B2[(8 * j + g) * NST + wo]);
            }
            #pragma unroll
            for (int j = 0; j < 8; j++)
                #pragma unroll
                for (int q = 0; q < 4; q++) {
                    int col = 8 * j + 2 * tig + (q & 1);
                    ho[j][q] = h[j][q] + cd2[j][q] + sb2[col];
                }
        }
        // R3: gates over [agg | ho]
        float cz[8][4] = {}, crr[8][4] = {}, cni[8][4] = {}, cnh[8][4] = {};
        const float* aggt = g_agg + (size_t)t * NV * 64;
        #pragma unroll
        for (int kt = 0; kt < 4; kt++) {
            float2 a0 = *(const float2*)(aggt + (size_t)grl * 64 + 16 * kt + 2 * tig);
            float2 a1 = *(const float2*)(aggt + (size_t)grh * 64 + 16 * kt + 2 * tig);
            float2 a2 = *(const float2*)(aggt + (size_t)grl * 64 + 16 * kt + 8 + 2 * tig);
            float2 a3 = *(const float2*)(aggt + (size_t)grh * 64 + 16 * kt + 8 + 2 * tig);
            u32 ah[4], al[4];
            pksplit(a0.x, a0.y, ah[0], al[0]);
            pksplit(a1.x, a1.y, ah[1], al[1]);
            pksplit(a2.x, a2.y, ah[2], al[2]);
            pksplit(a3.x, a3.y, ah[3], al[3]);
            int wo = 16 * kt + 4 * tig;
            #pragma unroll
            for (int j = 0; j < 8; j++) {
                mma3(cz[j], ah, al, &Bzr[(8 * j + g) * ZST + wo]);
                mma3(crr[j], ah, al, &Bzr[(64 + 8 * j + g) * ZST + wo]);
                mma3(cni[j], ah, al, &Bni[(8 * j + g) * NST + wo]);
            }
        }
        #pragma unroll
        for (int kt = 0; kt < 4; kt++) {
            u32 ah[4], al[4]; afrag(ho, kt, ah, al);
            int wo = 16 * (kt + 4) + 4 * tig;
            int wn = 16 * kt + 4 * tig;
            #pragma unroll
            for (int j = 0; j < 8; j++) {
                mma3(cz[j], ah, al, &Bzr[(8 * j + g) * ZST + wo]);
                mma3(crr[j], ah, al, &Bzr[(64 + 8 * j + g) * ZST + wo]);
                mma3(cnh[j], ah, al, &Bnh[(8 * j + g) * NST + wn]);
            }
        }
        #pragma unroll
        for (int j = 0; j < 8; j++)
            #pragma unroll
            for (int q = 0; q < 4; q++) {
                int col = 8 * j + 2 * tig + (q & 1);
                float z = sigf(cz[j][q] + sbg[col]);
                float r = sigf(crr[j][q] + sbg[64 + col]);
                float n = tanh_f(cni[j][q] + sbg[128 + col] + r * cnh[j][q]);
                h[j][q] = (1.f - z) * n + z * ho[j][q];
            }
    }
    // final decode h_{TT-1}
    {
        float cd[2][4] = {};
        #pragma unroll
        for (int kt = 0; kt < 4; kt++) {
            u32 ah[4], al[4]; afrag(h, kt, ah, al);
            int wo = 16 * kt + 4 * tig;
            #pragma unroll
            for (int j = 0; j < 2; j++) mma3(cd[j], ah, al, &B4[(8 * j + g) * NST + wo]);
        }
        #pragma unroll
        for (int j = 0; j < 2; j++)
            #pragma unroll
            for (int q = 0; q < 4; q++) {
                int row = (q < 2) ? grl : grh;
                int col = 8 * j + 2 * tig + (q & 1);
                out[((size_t)row * CC + col) * TT + (TT - 1)] = cd[j][q] + sbd[col];
            }
    }
}

// ---------------- launcher ----------------
extern "C" void kernel_launch(void* const* d_in, const int* in_sizes, int n_in,
                              void* d_out, int out_size) {
    const float* x    = (const float*)d_in[0];
    const int*   ei   = (const int*)d_in[1];
    const float* attr = (const float*)d_in[2];
    const float* Wenc = (const float*)d_in[3];
    const float* benc = (const float*)d_in[4];
    const float* Wgd  = (const float*)d_in[5];
    const float* gdWi = (const float*)d_in[6];
    const float* gdWh = (const float*)d_in[7];
    const float* gdb  = (const float*)d_in[8];
    const float* Wd1  = (const float*)d_in[9];
    const float* bd1  = (const float*)d_in[10];
    const float* Wd2  = (const float*)d_in[11];
    const float* bd2  = (const float*)d_in[12];
    const float* oW1  = (const float*)d_in[13];
    const float* ob1  = (const float*)d_in[14];
    const float* oW2  = (const float*)d_in[15];
    const float* ob2  = (const float*)d_in[16];
    const float* Wgc  = (const float*)d_in[17];
    const float* gcWi = (const float*)d_in[18];
    const float* gcWh = (const float*)d_in[19];
    const float* gcb  = (const float*)d_in[20];
    const float* Wdec = (const float*)d_in[21];
    const float* bdec = (const float*)d_in[22];
    float* out = (float*)d_out;

    int s1sz = (128 * ZST + 2 * 64 * NST + 192) * 4;
    int s2sz = (128 * ZST + 4 * 64 * NST + 16 * NST + 128 * 72 + 272) * 4;
    cudaFuncSetAttribute(k_scan1, cudaFuncAttributeMaxDynamicSharedMemorySize, s1sz);
    cudaFuncSetAttribute(k_zd,    cudaFuncAttributeMaxDynamicSharedMemorySize, 49920);
    cudaFuncSetAttribute(k_scan2, cudaFuncAttributeMaxDynamicSharedMemorySize, s2sz);

    k_enc<<<NV, 256>>>(x, Wenc, benc);                               // 0
    k_csr<<<1, 1024>>>(ei, attr, Wgd, gdWi, Wgc, gcWi);              // 1
    k_agg<<<4096, 256>>>();                                          // 2
    k_scan1<<<128, 256, s1sz>>>(gdWh, gdb);                          // 3
    k_zd<<<128, 256, 49920>>>(Wd1, bd1, Wd2, bd2, oW1, ob1);         // 4
    k_scan2<<<128, 256, s2sz>>>(gcWh, gcb, oW1, oW2, ob2, Wdec, bdec, out);  // 5
}

// round 16
// speedup vs baseline: 1.0878x; 1.0878x over previous
#include <cuda_runtime.h>
#include <cuda_bf16.h>

#define TT 150
#define VV 2048
#define CC 16
#define LL 64
#define EE 32768
#define NV 16384
#define L3 192
#define BS 72
#define NS 40

typedef unsigned long long u64;
typedef unsigned int u32;

__device__ float g_xe[(size_t)TT * NV * LL];
__device__ float g_agg[(size_t)TT * NV * LL];
__device__ float g_pre[NV * LL];
__device__ float g_Wgdi[LL * L3];
__device__ float g_Wgci[LL * L3];
__device__ int   g_off[VV + 1];
__device__ int   g_eid[EE];
__device__ u64   g_epk[EE];

__device__ __forceinline__ u64 pk2(float x, float y) {
    u64 r; asm("mov.b64 %0, {%1, %2};" : "=l"(r) : "f"(x), "f"(y)); return r;
}
__device__ __forceinline__ void upk2(u64 v, float& x, float& y) {
    asm("mov.b64 {%0, %1}, %2;" : "=f"(x), "=f"(y) : "l"(v));
}
__device__ __forceinline__ void fma2(u64& d, u64 a, u64 b) {
    asm("fma.rn.f32x2 %0, %1, %2, %0;" : "+l"(d) : "l"(a), "l"(b));
}
__device__ __forceinline__ float sigf(float x) {
    x = fminf(fmaxf(x, -20.f), 20.f);
    return __fdividef(1.f, 1.f + __expf(-x));
}
__device__ __forceinline__ float tanh_f(float x) {
    x = fminf(fmaxf(x, -10.f), 10.f);
    float e = __expf(-2.f * x);
    return __fdividef(1.f - e, 1.f + e);
}
__device__ __forceinline__ void pksplit(float x0, float x1, u32& ph, u32& pl) {
    u32 hp; asm("cvt.rn.bf16x2.f32 %0, %1, %2;" : "=r"(hp) : "f"(x1), "f"(x0));
    float h0 = __uint_as_float(hp << 16);
    float h1 = __uint_as_float(hp & 0xffff0000u);
    u32 lp; asm("cvt.rn.bf16x2.f32 %0, %1, %2;" : "=r"(lp) : "f"(x1 - h1), "f"(x0 - h0));
    ph = hp; pl = lp;
}
__device__ __forceinline__ void mma16816(float* c, const u32* a, const u32* b) {
    asm volatile("mma.sync.aligned.m16n8k16.row.col.f32.bf16.bf16.f32 "
        "{%0,%1,%2,%3}, {%4,%5,%6,%7}, {%8,%9}, {%0,%1,%2,%3};"
        : "+f"(c[0]), "+f"(c[1]), "+f"(c[2]), "+f"(c[3])
        : "r"(a[0]), "r"(a[1]), "r"(a[2]), "r"(a[3]), "r"(b[0]), "r"(b[1]));
}
__device__ __forceinline__ void afrag(const float v[8][4], int kt, u32* ah, u32* al) {
    #pragma unroll
    for (int i = 0; i < 4; i++) {
        int j = 2 * kt + (i >> 1);
        int q0 = (i & 1) * 2;
        pksplit(v[j][q0], v[j][q0 + 1], ah[i], al[i]);
    }
}
// 3-term split MMA from separate hi/lo arrays (validated R14 pattern)
__device__ __forceinline__ void mma3s(float* c, const u32* ah, const u32* al,
                                      const u32* ph, const u32* pl) {
    u32 bh[2] = { ph[0], ph[1] }, bl[2] = { pl[0], pl[1] };
    mma16816(c, ah, bh);
    mma16816(c, ah, bl);
    mma16816(c, al, bh);
}

// ---------------- encoder ----------------
__global__ void __launch_bounds__(256) k_enc(const float* __restrict__ x,
                                             const float* __restrict__ Wenc,
                                             const float* __restrict__ benc) {
    __shared__ float sx[CC * TT];
    __shared__ float2 sW[CC * 32];
    __shared__ float2 sb[32];
    int tid = threadIdx.x, r = blockIdx.x;
    for (int i = tid; i < CC * TT; i += 256) sx[i] = x[(size_t)r * CC * TT + i];
    for (int i = tid; i < CC * 32; i += 256) {
        int c = i >> 5, l = i & 31;
        sW[i] = make_float2(Wenc[c * LL + l], Wenc[c * LL + l + 32]);
    }
    if (tid < 32) sb[tid] = make_float2(benc[tid], benc[tid + 32]);
    __syncthreads();
    int wid = tid >> 5, lane = tid & 31;
    for (int t = wid; t < TT; t += 8) {
        u64 acc = pk2(sb[lane].x, sb[lane].y);
        #pragma unroll
        for (int c = 0; c < CC; c++) {
            float xs = sx[c * TT + t];
            fma2(acc, pk2(xs, xs), pk2(sW[c * 32 + lane].x, sW[c * 32 + lane].y));
        }
        float ax, ay; upk2(acc, ax, ay);
        size_t o = ((size_t)t * NV + r) * LL;
        g_xe[o + lane] = ax;
        g_xe[o + lane + 32] = ay;
    }
}

// ---------------- fused CSR build + weight combines + edge packing ----------------
__global__ void __launch_bounds__(1024) k_csr(const int* __restrict__ ei,
        const float* __restrict__ attr,
        const float* __restrict__ Wgd, const float* __restrict__ gdWi,
        const float* __restrict__ Wgc, const float* __restrict__ gcWi) {
    __shared__ int scnt[VV];
    __shared__ int sfil[VV];
    int tid = threadIdx.x;
    for (int i = tid; i < VV; i += 1024) { scnt[i] = 0; sfil[i] = 0; }
    __syncthreads();
    for (int e = tid; e < EE; e += 1024) atomicAdd(&scnt[ei[EE + e]], 1);
    __syncthreads();
    if (tid == 0) {
        int acc = 0;
        for (int v = 0; v < VV; v++) { g_off[v] = acc; acc += scnt[v]; }
        g_off[VV] = acc;
    }
    __syncthreads();
    for (int e = tid; e < EE; e += 1024) {
        int d = ei[EE + e];
        int p = g_off[d] + atomicAdd(&sfil[d], 1);
        g_eid[p] = e;
    }
    __syncthreads();
    for (int v = tid; v < VV; v += 1024) {
        int s = g_off[v], en = g_off[v + 1];
        for (int i = s + 1; i < en; i++) {
            int key = g_eid[i];
            int j = i - 1;
            while (j >= s && g_eid[j] > key) { g_eid[j + 1] = g_eid[j]; j--; }
            g_eid[j + 1] = key;
        }
    }
    __syncthreads();
    for (int p = tid; p < EE; p += 1024) {
        int e = g_eid[p];
        g_epk[p] = (u64)(u32)ei[e] | ((u64)__float_as_uint(attr[e]) << 32);
    }
    for (int idx = tid; idx < 2 * LL * L3; idx += 1024) {
        int which = idx >= LL * L3;
        int rem = which ? idx - LL * L3 : idx;
        int k = rem / L3, j = rem - k * L3;
        const float* A = which ? Wgc : Wgd;
        const float* B = which ? gcWi : gdWi;
        float acc = 0.f;
        #pragma unroll 8
        for (int m = 0; m < LL; m++) acc = fmaf(A[k * LL + m], B[m * L3 + j], acc);
        (which ? g_Wgci : g_Wgdi)[rem] = acc;
    }
}

// ---------------- aggregation (packed edges, 2x unroll) ----------------
__global__ void __launch_bounds__(256) k_agg() {
    int tid = threadIdx.x, wid = tid >> 5, lane = tid & 31;
    int gw = blockIdx.x * 8 + wid, nw = gridDim.x * 8;
    for (int task = gw; task < TT * NV; task += nw) {
        int t = task >> 14;
        int r = task & (NV - 1);
        int v = r & (VV - 1);
        const float* xb = g_xe + ((size_t)t * NV + (r & ~(VV - 1))) * LL;
        int s0 = g_off[v], s1 = g_off[v + 1];
        u64 acc = 0ULL, acc2 = 0ULL;
        int e = s0;
        for (; e + 1 < s1; e += 2) {
            u64 p0 = g_epk[e], p1 = g_epk[e + 1];
            int sA = (int)(u32)(p0 & 0xffffffffu);
            int sB = (int)(u32)(p1 & 0xffffffffu);
            float wA = __uint_as_float((u32)(p0 >> 32));
            float wB = __uint_as_float((u32)(p1 >> 32));
            float2 vA = ((const float2*)(xb + (size_t)sA * LL))[lane];
            float2 vB = ((const float2*)(xb + (size_t)sB * LL))[lane];
            fma2(acc, pk2(wA, wA), pk2(vA.x, vA.y));
            fma2(acc2, pk2(wB, wB), pk2(vB.x, vB.y));
        }
        if (e < s1) {
            u64 p0 = g_epk[e];
            int sA = (int)(u32)(p0 & 0xffffffffu);
            float wA = __uint_as_float((u32)(p0 >> 32));
            float2 vA = ((const float2*)(xb + (size_t)sA * LL))[lane];
            fma2(acc, pk2(wA, wA), pk2(vA.x, vA.y));
        }
        float a0, a1, b0, b1; upk2(acc, a0, a1); upk2(acc2, b0, b1);
        ((float2*)(g_agg + (size_t)task * LL))[lane] = make_float2(a0 + b0, a1 + b1);
    }
}

// ---------------- scan1: HMMA register-chained domain GRU + fused z_D epilogue ----------------
__global__ void __launch_bounds__(256, 1) k_scan1(const float* __restrict__ Wh,
                                                  const float* __restrict__ bg,
                                                  const float* __restrict__ Wd1, const float* __restrict__ bd1,
                                                  const float* __restrict__ Wd2, const float* __restrict__ bd2,
                                                  const float* __restrict__ oW1, const float* __restrict__ ob1) {
    extern __shared__ u32 s1m[];
    u32* Bzrh = s1m;                    // 128*BS
    u32* Bzrl = Bzrh + 128 * BS;
    u32* Bnih = Bzrl + 128 * BS;        // 64*NS
    u32* Bnil = Bnih + 64 * NS;
    u32* Bnhh = Bnil + 64 * NS;
    u32* Bnhl = Bnhh + 64 * NS;
    u32* D1h  = Bnhl + 64 * NS;
    u32* D1l  = D1h + 64 * NS;
    u32* D2h  = D1l + 64 * NS;
    u32* D2l  = D2h + 64 * NS;
    u32* O1h  = D2l + 64 * NS;
    u32* O1l  = O1h + 64 * NS;
    float* sbg = (float*)(O1l + 64 * NS);   // 192
    float* sbz = sbg + 192;                 // 192: bd1|bd2|ob1
    int tid = threadIdx.x;
    for (int i = tid; i < 128 * 64; i += 256) {
        int c = i >> 6, w = i & 63;
        int k0 = 16 * (w >> 3) + ((w & 7) & ~1) + 8 * (w & 1);
        float v0 = (k0 < 64) ? g_Wgdi[k0 * L3 + c] : Wh[(k0 - 64) * L3 + c];
        float v1 = (k0 + 1 < 64) ? g_Wgdi[(k0 + 1) * L3 + c] : Wh[(k0 + 1 - 64) * L3 + c];
        pksplit(v0, v1, Bzrh[c * BS + w], Bzrl[c * BS + w]);
    }
    for (int i = tid; i < 64 * 32; i += 256) {
        int c = i >> 5, w = i & 31;
        int k0 = 16 * (w >> 3) + ((w & 7) & ~1) + 8 * (w & 1);
        pksplit(g_Wgdi[k0 * L3 + 128 + c], g_Wgdi[(k0 + 1) * L3 + 128 + c],
                Bnih[c * NS + w], Bnil[c * NS + w]);
        pksplit(Wh[k0 * L3 + 128 + c], Wh[(k0 + 1) * L3 + 128 + c],
                Bnhh[c * NS + w], Bnhl[c * NS + w]);
        pksplit(Wd1[k0 * 64 + c], Wd1[(k0 + 1) * 64 + c],
                D1h[c * NS + w], D1l[c * NS + w]);
        pksplit(Wd2[k0 * 64 + c], Wd2[(k0 + 1) * 64 + c],
                D2h[c * NS + w], D2l[c * NS + w]);
        pksplit(oW1[(64 + k0) * 64 + c], oW1[(64 + k0 + 1) * 64 + c],
                O1h[c * NS + w], O1l[c * NS + w]);
    }
    if (tid < 192) sbg[tid] = bg[tid];
    if (tid < 64) sbz[tid] = bd1[tid];
    else if (tid < 128) sbz[tid] = bd2[tid - 64];
    else if (tid < 192) sbz[tid] = ob1[tid - 128];
    __syncthreads();
    int lane = tid & 31, wid = tid >> 5;
    int g = lane >> 2, tig = lane & 3;
    int grl = blockIdx.x * 128 + wid * 16 + g, grh = grl + 8;
    float h[8][4];
    #pragma unroll
    for (int j = 0; j < 8; j++)
        #pragma unroll
        for (int q = 0; q < 4; q++) h[j][q] = 0.f;
    for (int t = 0; t < TT; t++) {
        float cz[8][4] = {}, crr[8][4] = {}, cni[8][4] = {}, cnh[8][4] = {};
        const float* aggt = g_agg + (size_t)t * NV * 64;
        #pragma unroll
        for (int kt = 0; kt < 4; kt++) {
            float2 a0 = *(const float2*)(aggt + (size_t)grl * 64 + 16 * kt + 2 * tig);
            float2 a1 = *(const float2*)(aggt + (size_t)grh * 64 + 16 * kt + 2 * tig);
            float2 a2 = *(const float2*)(aggt + (size_t)grl * 64 + 16 * kt + 8 + 2 * tig);
            float2 a3 = *(const float2*)(aggt + (size_t)grh * 64 + 16 * kt + 8 + 2 * tig);
            u32 ah[4], al[4];
            pksplit(a0.x, a0.y, ah[0], al[0]);
            pksplit(a1.x, a1.y, ah[1], al[1]);
            pksplit(a2.x, a2.y, ah[2], al[2]);
            pksplit(a3.x, a3.y, ah[3], al[3]);
            int wo = 8 * kt + 2 * tig;
            #pragma unroll
            for (int j = 0; j < 8; j++) {
                mma3s(cz[j], ah, al, &Bzrh[(8 * j + g) * BS + wo], &Bzrl[(8 * j + g) * BS + wo]);
                mma3s(crr[j], ah, al, &Bzrh[(64 + 8 * j + g) * BS + wo], &Bzrl[(64 + 8 * j + g) * BS + wo]);
                mma3s(cni[j], ah, al, &Bnih[(8 * j + g) * NS + wo], &Bnil[(8 * j + g) * NS + wo]);
            }
        }
        #pragma unroll
        for (int kt = 4; kt < 8; kt++) {
            u32 ah[4], al[4]; afrag(h, kt - 4, ah, al);
            int wo = 8 * kt + 2 * tig;
            int wn = 8 * (kt - 4) + 2 * tig;
            #pragma unroll
            for (int j = 0; j < 8; j++) {
                mma3s(cz[j], ah, al, &Bzrh[(8 * j + g) * BS + wo], &Bzrl[(8 * j + g) * BS + wo]);
                mma3s(crr[j], ah, al, &Bzrh[(64 + 8 * j + g) * BS + wo], &Bzrl[(64 + 8 * j + g) * BS + wo]);
                mma3s(cnh[j], ah, al, &Bnhh[(8 * j + g) * NS + wn], &Bnhl[(8 * j + g) * NS + wn]);
            }
        }
        #pragma unroll
        for (int j = 0; j < 8; j++)
            #pragma unroll
            for (int q = 0; q < 4; q++) {
                int col = 8 * j + 2 * tig + (q & 1);
                float z = sigf(cz[j][q] + sbg[col]);
                float r = sigf(crr[j][q] + sbg[64 + col]);
                float n = tanh_f(cni[j][q] + sbg[128 + col] + r * cnh[j][q]);
                h[j][q] = (1.f - z) * n + z * h[j][q];
            }
    }
    // ---- fused z_D epilogue: pre = (tanh(h@Wd1+bd1)@Wd2+bd2)@W1bot+ob1 ----
    float u1[8][4];
    {
        float cu[8][4] = {};
        #pragma unroll
        for (int kt = 0; kt < 4; kt++) {
            u32 ah[4], al[4]; afrag(h, kt, ah, al);
            int wo = 8 * kt + 2 * tig;
            #pragma unroll
            for (int j = 0; j < 8; j++)
                mma3s(cu[j], ah, al, &D1h[(8 * j + g) * NS + wo], &D1l[(8 * j + g) * NS + wo]);
        }
        #pragma unroll
        for (int j = 0; j < 8; j++)
            #pragma unroll
            for (int q = 0; q < 4; q++)
                u1[j][q] = tanh_f(cu[j][q] + sbz[8 * j + 2 * tig + (q & 1)]);
    }
    float v2[8][4];
    {
        float cv[8][4] = {};
        #pragma unroll
        for (int kt = 0; kt < 4; kt++) {
            u32 ah[4], al[4]; afrag(u1, kt, ah, al);
            int wo = 8 * kt + 2 * tig;
            #pragma unroll
            for (int j = 0; j < 8; j++)
                mma3s(cv[j], ah, al, &D2h[(8 * j + g) * NS + wo], &D2l[(8 * j + g) * NS + wo]);
        }
        #pragma unroll
        for (int j = 0; j < 8; j++)
            #pragma unroll
            for (int q = 0; q < 4; q++)
                v2[j][q] = cv[j][q] + sbz[64 + 8 * j + 2 * tig + (q & 1)];
    }
    {
        float cp[8][4] = {};
        #pragma unroll
        for (int kt = 0; kt < 4; kt++) {
            u32 ah[4], al[4]; afrag(v2, kt, ah, al);
            int wo = 8 * kt + 2 * tig;
            #pragma unroll
            for (int j = 0; j < 8; j++)
                mma3s(cp[j], ah, al, &O1h[(8 * j + g) * NS + wo], &O1l[(8 * j + g) * NS + wo]);
        }
        #pragma unroll
        for (int j = 0; j < 8; j++)
            #pragma unroll
            for (int q = 0; q < 4; q++) {
                int row = (q < 2) ? grl : grh;
                int col = 8 * j + 2 * tig + (q & 1);
                g_pre[(size_t)row * 64 + col] = cp[j][q] + sbz[128 + col];
            }
    }
}

// ---------------- scan2: HMMA register-chained main scan (validated R14 version) ----------------
__global__ void __launch_bounds__(256, 1) k_scan2(
        const float* __restrict__ Wh, const float* __restrict__ bgc,
        const float* __restrict__ oW1, const float* __restrict__ oW2,
        const float* __restrict__ ob2,
        const float* __restrict__ Wdec, const float* __restrict__ bdec,
        float* __restrict__ out) {
    extern __shared__ u32 s2[];
    u32* Bzrh = s2;
    u32* Bzrl = Bzrh + 128 * BS;
    u32* Bnih = Bzrl + 128 * BS;
    u32* Bnil = Bnih + 64 * NS;
    u32* Bnhh = Bnil + 64 * NS;
    u32* Bnhl = Bnhh + 64 * NS;
    u32* B1h  = Bnhl + 64 * NS;
    u32* B1l  = B1h + 64 * NS;
    u32* B2h  = B1l + 64 * NS;
    u32* B2l  = B2h + 64 * NS;
    u32* B4h  = B2l + 64 * NS;
    u32* B4l  = B4h + 16 * NS;
    float* spre = (float*)(B4l + 16 * NS);  // stride 72 floats
    float* sbg  = spre + 128 * BS;
    float* sb2  = sbg + 192;
    float* sbd  = sb2 + 64;
    int tid = threadIdx.x;
    for (int i = tid; i < 128 * 64; i += 256) {
        int c = i >> 6, w = i & 63;
        int k0 = 16 * (w >> 3) + ((w & 7) & ~1) + 8 * (w & 1);
        float v0 = (k0 < 64) ? g_Wgci[k0 * L3 + c] : Wh[(k0 - 64) * L3 + c];
        float v1 = (k0 + 1 < 64) ? g_Wgci[(k0 + 1) * L3 + c] : Wh[(k0 + 1 - 64) * L3 + c];
        pksplit(v0, v1, Bzrh[c * BS + w], Bzrl[c * BS + w]);
    }
    for (int i = tid; i < 64 * 32; i += 256) {
        int c = i >> 5, w = i & 31;
        int k0 = 16 * (w >> 3) + ((w & 7) & ~1) + 8 * (w & 1);
        pksplit(g_Wgci[k0 * L3 + 128 + c], g_Wgci[(k0 + 1) * L3 + 128 + c],
                Bnih[c * NS + w], Bnil[c * NS + w]);
        pksplit(Wh[k0 * L3 + 128 + c], Wh[(k0 + 1) * L3 + 128 + c],
                Bnhh[c * NS + w], Bnhl[c * NS + w]);
        pksplit(oW1[k0 * 64 + c], oW1[(k0 + 1) * 64 + c],
                B1h[c * NS + w], B1l[c * NS + w]);
        pksplit(oW2[k0 * 64 + c], oW2[(k0 + 1) * 64 + c],
                B2h[c * NS + w], B2l[c * NS + w]);
    }
    for (int i = tid; i < 16 * 32; i += 256) {
        int c = i >> 5, w = i & 31;
        int k0 = 16 * (w >> 3) + ((w & 7) & ~1) + 8 * (w & 1);
        pksplit(Wdec[k0 * CC + c], Wdec[(k0 + 1) * CC + c],
                B4h[c * NS + w], B4l[c * NS + w]);
    }
    int R0b = blockIdx.x * 128;
    for (int i = tid; i < 128 * 32; i += 256) {
        int r = i >> 5, p = i & 31;
        ((float2*)spre)[r * 36 + p] = ((const float2*)(g_pre + (size_t)(R0b + r) * 64))[p];
    }
    if (tid < 192) sbg[tid] = bgc[tid];
    if (tid < 64) sb2[tid] = ob2[tid];
    if (tid < 16) sbd[tid] = bdec[tid];
    __syncthreads();

    int lane = tid & 31, wid = tid >> 5;
    int g = lane >> 2, tig = lane & 3;
    int rl = wid * 16 + g, rh = rl + 8;
    int grl = R0b + rl, grh = R0b + rh;
    float h[8][4];
    #pragma unroll
    for (int j = 0; j < 8; j++) {
        float2 a = *(const float2*)(g_xe + (size_t)grl * 64 + 8 * j + 2 * tig);
        float2 b = *(const float2*)(g_xe + (size_t)grh * 64 + 8 * j + 2 * tig);
        h[j][0] = a.x; h[j][1] = a.y; h[j][2] = b.x; h[j][3] = b.y;
    }
    {
        float cd[2][4] = {};
        #pragma unroll
        for (int kt = 0; kt < 4; kt++) {
            u32 ah[4], al[4]; afrag(h, kt, ah, al);
            int wo = 8 * kt + 2 * tig;
            #pragma unroll
            for (int j = 0; j < 2; j++)
                mma3s(cd[j], ah, al, &B4h[(8 * j + g) * NS + wo], &B4l[(8 * j + g) * NS + wo]);
        }
        #pragma unroll
        for (int j = 0; j < 2; j++)
            #pragma unroll
            for (int q = 0; q < 4; q++) {
                int row = (q < 2) ? grl : grh;
                int col = 8 * j + 2 * tig + (q & 1);
                out[((size_t)row * CC + col) * TT] = cd[j][q] + sbd[col];
            }
    }
    for (int t = 1; t < TT; t++) {
        float cu[8][4] = {};
        #pragma unroll
        for (int kt = 0; kt < 4; kt++) {
            u32 ah[4], al[4]; afrag(h, kt, ah, al);
            int wo = 8 * kt + 2 * tig;
            #pragma unroll
            for (int j = 0; j < 8; j++)
                mma3s(cu[j], ah, al, &B1h[(8 * j + g) * NS + wo], &B1l[(8 * j + g) * NS + wo]);
        }
        float uf[8][4];
        #pragma unroll
        for (int j = 0; j < 8; j++) {
            float2 p0 = ((const float2*)spre)[rl * 36 + 4 * j + tig];
            float2 p1 = ((const float2*)spre)[rh * 36 + 4 * j + tig];
            uf[j][0] = tanh_f(cu[j][0] + p0.x); uf[j][1] = tanh_f(cu[j][1] + p0.y);
            uf[j][2] = tanh_f(cu[j][2] + p1.x); uf[j][3] = tanh_f(cu[j][3] + p1.y);
        }
        float ho[8][4];
        {
            float cd2[8][4] = {};
            #pragma unroll
            for (int kt = 0; kt < 4; kt++) {
                u32 ah[4], al[4]; afrag(uf, kt, ah, al);
                int wo = 8 * kt + 2 * tig;
                #pragma unroll
                for (int j = 0; j < 8; j++)
                    mma3s(cd2[j], ah, al, &B2h[(8 * j + g) * NS + wo], &B2l[(8 * j + g) * NS + wo]);
            }
            #pragma unroll
            for (int j = 0; j < 8; j++)
                #pragma unroll
                for (int q = 0; q < 4; q++) {
                    int col = 8 * j + 2 * tig + (q & 1);
                    ho[j][q] = h[j][q] + cd2[j][q] + sb2[col];
                }
        }
        float cz[8][4] = {}, crr[8][4] = {}, cni[8][4] = {}, cnh[8][4] = {};
        const float* aggt = g_agg + (size_t)t * NV * 64;
        #pragma unroll
        for (int kt = 0; kt < 4; kt++) {
            float2 a0 = *(const float2*)(aggt + (size_t)grl * 64 + 16 * kt + 2 * tig);
            float2 a1 = *(const float2*)(aggt + (size_t)grh * 64 + 16 * kt + 2 * tig);
            float2 a2 = *(const float2*)(aggt + (size_t)grl * 64 + 16 * kt + 8 + 2 * tig);
            float2 a3 = *(const float2*)(aggt + (size_t)grh * 64 + 16 * kt + 8 + 2 * tig);
            u32 ah[4], al[4];
            pksplit(a0.x, a0.y, ah[0], al[0]);
            pksplit(a1.x, a1.y, ah[1], al[1]);
            pksplit(a2.x, a2.y, ah[2], al[2]);
            pksplit(a3.x, a3.y, ah[3], al[3]);
            int wo = 8 * kt + 2 * tig;
            #pragma unroll
            for (int j = 0; j < 8; j++) {
                mma3s(cz[j], ah, al, &Bzrh[(8 * j + g) * BS + wo], &Bzrl[(8 * j + g) * BS + wo]);
                mma3s(crr[j], ah, al, &Bzrh[(64 + 8 * j + g) * BS + wo], &Bzrl[(64 + 8 * j + g) * BS + wo]);
                mma3s(cni[j], ah, al, &Bnih[(8 * j + g) * NS + wo], &Bnil[(8 * j + g) * NS + wo]);
            }
        }
        #pragma unroll
        for (int kt = 4; kt < 8; kt++) {
            u32 ah[4], al[4]; afrag(ho, kt - 4, ah, al);
            int wo = 8 * kt + 2 * tig;
            int wn = 8 * (kt - 4) + 2 * tig;
            #pragma unroll
            for (int j = 0; j < 8; j++) {
                mma3s(cz[j], ah, al, &Bzrh[(8 * j + g) * BS + wo], &Bzrl[(8 * j + g) * BS + wo]);
                mma3s(crr[j], ah, al, &Bzrh[(64 + 8 * j + g) * BS + wo], &Bzrl[(64 + 8 * j + g) * BS + wo]);
                mma3s(cnh[j], ah, al, &Bnhh[(8 * j + g) * NS + wn], &Bnhl[(8 * j + g) * NS + wn]);
            }
        }
        #pragma unroll
        for (int j = 0; j < 8; j++)
            #pragma unroll
            for (int q = 0; q < 4; q++) {
                int col = 8 * j + 2 * tig + (q & 1);
                float z = sigf(cz[j][q] + sbg[col]);
                float r = sigf(crr[j][q] + sbg[64 + col]);
                float n = tanh_f(cni[j][q] + sbg[128 + col] + r * cnh[j][q]);
                h[j][q] = (1.f - z) * n + z * ho[j][q];
            }
        float cd[2][4] = {};
        #pragma unroll
        for (int kt = 0; kt < 4; kt++) {
            u32 ah[4], al[4]; afrag(h, kt, ah, al);
            int wo = 8 * kt + 2 * tig;
            #pragma unroll
            for (int j = 0; j < 2; j++)
                mma3s(cd[j], ah, al, &B4h[(8 * j + g) * NS + wo], &B4l[(8 * j + g) * NS + wo]);
        }
        #pragma unroll
        for (int j = 0; j < 2; j++)
            #pragma unroll
            for (int q = 0; q < 4; q++) {
                int row = (q < 2) ? grl : grh;
                int col = 8 * j + 2 * tig + (q & 1);
                out[((size_t)row * CC + col) * TT + t] = cd[j][q] + sbd[col];
            }
    }
}

// ---------------- launcher ----------------
extern "C" void kernel_launch(void* const* d_in, const int* in_sizes, int n_in,
                              void* d_out, int out_size) {
    const float* x    = (const float*)d_in[0];
    const int*   ei   = (const int*)d_in[1];
    const float* attr = (const float*)d_in[2];
    const float* Wenc = (const float*)d_in[3];
    const float* benc = (const float*)d_in[4];
    const float* Wgd  = (const float*)d_in[5];
    const float* gdWi = (const float*)d_in[6];
    const float* gdWh = (const float*)d_in[7];
    const float* gdb  = (const float*)d_in[8];
    const float* Wd1  = (const float*)d_in[9];
    const float* bd1  = (const float*)d_in[10];
    const float* Wd2  = (const float*)d_in[11];
    const float* bd2  = (const float*)d_in[12];
    const float* oW1  = (const float*)d_in[13];
    const float* ob1  = (const float*)d_in[14];
    const float* oW2  = (const float*)d_in[15];
    const float* ob2  = (const float*)d_in[16];
    const float* Wgc  = (const float*)d_in[17];
    const float* gcWi = (const float*)d_in[18];
    const float* gcWh = (const float*)d_in[19];
    const float* gcb  = (const float*)d_in[20];
    const float* Wdec = (const float*)d_in[21];
    const float* bdec = (const float*)d_in[22];
    float* out = (float*)d_out;

    int s1sz = (2 * 128 * BS + 10 * 64 * NS + 384) * 4;
    int s2sz = (2 * 128 * BS + 8 * 64 * NS + 2 * 16 * NS + 128 * BS + 272) * 4;
    cudaFuncSetAttribute(k_scan1, cudaFuncAttributeMaxDynamicSharedMemorySize, s1sz);
    cudaFuncSetAttribute(k_scan2, cudaFuncAttributeMaxDynamicSharedMemorySize, s2sz);

    k_enc<<<NV, 256>>>(x, Wenc, benc);                               // 0
    k_csr<<<1, 1024>>>(ei, attr, Wgd, gdWi, Wgc, gcWi);              // 1
    k_agg<<<4096, 256>>>();                                          // 2
    k_scan1<<<128, 256, s1sz>>>(gdWh, gdb, Wd1, bd1, Wd2, bd2, oW1, ob1);  // 3
    k_scan2<<<128, 256, s2sz>>>(gcWh, gcb, oW1, oW2, ob2, Wdec, bdec, out);  // 4
}